// round 1
// baseline (speedup 1.0000x reference)
#include <cuda_runtime.h>

// Problem constants: B=2, H=16, S=2048, D=128, fp32.
#define SS     2048
#define DD     128
#define NHEAD  32                       // B*H
#define SCALE  0.08838834764831845f     // 1/sqrt(128)

// ---------------------------------------------------------------------------
// Kernel A: W = SCALE * Q @ K^T   (per head)
// Tiles: 128x128 output, K-step 32. 256 threads, 8x8 per thread.
// grid (SS/128, SS/128, NHEAD)
// ---------------------------------------------------------------------------
__global__ __launch_bounds__(256) void qk_kernel(
    const float* __restrict__ Q, const float* __restrict__ K,
    float* __restrict__ W)
{
    __shared__ float Qs[32][128];
    __shared__ float Ks[32][128];

    const int tid  = threadIdx.x;
    const int tx   = tid & 15;      // 0..15
    const int ty   = tid >> 4;      // 0..15
    const int head = blockIdx.z;
    const int rowBase = blockIdx.y * 128;
    const int colBase = blockIdx.x * 128;

    const float* q = Q + (size_t)head * SS * DD;
    const float* k = K + (size_t)head * SS * DD;
    float*       w = W + (size_t)head * SS * SS;

    float acc[8][8];
#pragma unroll
    for (int i = 0; i < 8; i++)
#pragma unroll
        for (int j = 0; j < 8; j++) acc[i][j] = 0.0f;

#pragma unroll
    for (int kk = 0; kk < DD; kk += 32) {
        // Load 128x32 tiles of Q and K, store transposed [k][m].
#pragma unroll
        for (int p = 0; p < 4; p++) {
            int pos = tid + p * 256;          // 0..1023 float4 slots
            int r   = pos >> 3;               // 0..127
            int c4  = pos & 7;                // 0..7 (float4 within 32-col row)
            float4 qv = *(const float4*)(q + (size_t)(rowBase + r) * DD + kk + c4 * 4);
            Qs[c4 * 4 + 0][r] = qv.x;
            Qs[c4 * 4 + 1][r] = qv.y;
            Qs[c4 * 4 + 2][r] = qv.z;
            Qs[c4 * 4 + 3][r] = qv.w;
            float4 kv = *(const float4*)(k + (size_t)(colBase + r) * DD + kk + c4 * 4);
            Ks[c4 * 4 + 0][r] = kv.x;
            Ks[c4 * 4 + 1][r] = kv.y;
            Ks[c4 * 4 + 2][r] = kv.z;
            Ks[c4 * 4 + 3][r] = kv.w;
        }
        __syncthreads();

#pragma unroll
        for (int k2 = 0; k2 < 32; k2++) {
            float a[8], b[8];
            *(float4*)(a)     = *(const float4*)&Qs[k2][ty * 8];
            *(float4*)(a + 4) = *(const float4*)&Qs[k2][ty * 8 + 4];
            *(float4*)(b)     = *(const float4*)&Ks[k2][tx * 8];
            *(float4*)(b + 4) = *(const float4*)&Ks[k2][tx * 8 + 4];
#pragma unroll
            for (int i = 0; i < 8; i++)
#pragma unroll
                for (int j = 0; j < 8; j++)
                    acc[i][j] = fmaf(a[i], b[j], acc[i][j]);
        }
        __syncthreads();
    }

#pragma unroll
    for (int i = 0; i < 8; i++) {
        size_t row = (size_t)(rowBase + ty * 8 + i);
#pragma unroll
        for (int j4 = 0; j4 < 8; j4 += 4) {
            float4 o;
            o.x = acc[i][j4 + 0] * SCALE;
            o.y = acc[i][j4 + 1] * SCALE;
            o.z = acc[i][j4 + 2] * SCALE;
            o.w = acc[i][j4 + 3] * SCALE;
            *(float4*)(w + row * SS + colBase + tx * 8 + j4) = o;
        }
    }
}

// ---------------------------------------------------------------------------
// Kernel B: in-place row softmax of W. One block per row (256 thr, 8 elem/thr).
// grid (SS, NHEAD)
// ---------------------------------------------------------------------------
__global__ __launch_bounds__(256) void softmax_kernel(float* __restrict__ W)
{
    const int tid = threadIdx.x;
    float* w = W + ((size_t)blockIdx.y * SS + blockIdx.x) * SS;

    float v[8];
#pragma unroll
    for (int i = 0; i < 8; i++) v[i] = w[tid + i * 256];

    // row max
    float m = v[0];
#pragma unroll
    for (int i = 1; i < 8; i++) m = fmaxf(m, v[i]);
#pragma unroll
    for (int o = 16; o > 0; o >>= 1) m = fmaxf(m, __shfl_xor_sync(0xffffffffu, m, o));

    __shared__ float red[8];
    if ((tid & 31) == 0) red[tid >> 5] = m;
    __syncthreads();
    float m2 = red[0];
#pragma unroll
    for (int i = 1; i < 8; i++) m2 = fmaxf(m2, red[i]);
    __syncthreads();   // protect red before reuse

    // exp + row sum
    float s = 0.0f;
#pragma unroll
    for (int i = 0; i < 8; i++) { v[i] = __expf(v[i] - m2); s += v[i]; }
#pragma unroll
    for (int o = 16; o > 0; o >>= 1) s += __shfl_xor_sync(0xffffffffu, s, o);
    if ((tid & 31) == 0) red[tid >> 5] = s;
    __syncthreads();
    float total = 0.0f;
#pragma unroll
    for (int i = 0; i < 8; i++) total += red[i];

    float inv = 1.0f / total;
#pragma unroll
    for (int i = 0; i < 8; i++) w[tid + i * 256] = v[i] * inv;
}

// ---------------------------------------------------------------------------
// Kernel C: O = P @ V   (per head).  M=2048 (rows/128 per block), N=128=D,
// K=2048 in steps of 32. 256 threads, 8x8 per thread.
// grid (SS/128, NHEAD)
// ---------------------------------------------------------------------------
__global__ __launch_bounds__(256) void pv_kernel(
    const float* __restrict__ P, const float* __restrict__ V,
    float* __restrict__ O)
{
    __shared__ float Ps[32][128];
    __shared__ float Vs[32][128];

    const int tid  = threadIdx.x;
    const int tx   = tid & 15;
    const int ty   = tid >> 4;
    const int head = blockIdx.y;
    const int rowBase = blockIdx.x * 128;

    const float* p = P + (size_t)head * SS * SS;
    const float* v = V + (size_t)head * SS * DD;
    float*       o = O + (size_t)head * SS * DD;

    float acc[8][8];
#pragma unroll
    for (int i = 0; i < 8; i++)
#pragma unroll
        for (int j = 0; j < 8; j++) acc[i][j] = 0.0f;

    for (int kk = 0; kk < SS; kk += 32) {
#pragma unroll
        for (int p4 = 0; p4 < 4; p4++) {
            int pos = tid + p4 * 256;
            {   // P tile 128x32 (row stride SS), transpose to Ps[k][m]
                int r  = pos >> 3;
                int c4 = pos & 7;
                float4 pv4 = *(const float4*)(p + (size_t)(rowBase + r) * SS + kk + c4 * 4);
                Ps[c4 * 4 + 0][r] = pv4.x;
                Ps[c4 * 4 + 1][r] = pv4.y;
                Ps[c4 * 4 + 2][r] = pv4.z;
                Ps[c4 * 4 + 3][r] = pv4.w;
            }
            {   // V tile 32x128, direct [k][n]
                int r  = pos >> 5;   // 0..31
                int c4 = pos & 31;   // 0..31
                float4 vv = *(const float4*)(v + (size_t)(kk + r) * DD + c4 * 4);
                *(float4*)&Vs[r][c4 * 4] = vv;
            }
        }
        __syncthreads();

#pragma unroll
        for (int k2 = 0; k2 < 32; k2++) {
            float a[8], b[8];
            *(float4*)(a)     = *(const float4*)&Ps[k2][ty * 8];
            *(float4*)(a + 4) = *(const float4*)&Ps[k2][ty * 8 + 4];
            *(float4*)(b)     = *(const float4*)&Vs[k2][tx * 8];
            *(float4*)(b + 4) = *(const float4*)&Vs[k2][tx * 8 + 4];
#pragma unroll
            for (int i = 0; i < 8; i++)
#pragma unroll
                for (int j = 0; j < 8; j++)
                    acc[i][j] = fmaf(a[i], b[j], acc[i][j]);
        }
        __syncthreads();
    }

#pragma unroll
    for (int i = 0; i < 8; i++) {
        size_t row = (size_t)(rowBase + ty * 8 + i);
#pragma unroll
        for (int j4 = 0; j4 < 8; j4 += 4) {
            float4 ov;
            ov.x = acc[i][j4 + 0];
            ov.y = acc[i][j4 + 1];
            ov.z = acc[i][j4 + 2];
            ov.w = acc[i][j4 + 3];
            *(float4*)(o + row * DD + tx * 8 + j4) = ov;
        }
    }
}

// ---------------------------------------------------------------------------
extern "C" void kernel_launch(void* const* d_in, const int* in_sizes, int n_in,
                              void* d_out, int out_size)
{
    const float* Q = (const float*)d_in[0];
    const float* K = (const float*)d_in[1];
    const float* V = (const float*)d_in[2];

    float* O = (float*)d_out;                              // [B,H,S,D]
    float* W = (float*)d_out + (size_t)NHEAD * SS * DD;    // [B,H,S,S]

    dim3 blk(256);
    qk_kernel<<<dim3(SS / 128, SS / 128, NHEAD), blk>>>(Q, K, W);
    softmax_kernel<<<dim3(SS, NHEAD), blk>>>(W);
    pv_kernel<<<dim3(SS / 128, NHEAD), blk>>>(W, V, O);
}

// round 3
// speedup vs baseline: 3.7638x; 3.7638x over previous
#include <cuda_runtime.h>
#include <cuda_bf16.h>

#define SS     2048
#define DD     128
#define NHEAD  32
#define SCALE  0.08838834764831845f

// ---------------------------------------------------------------------------
// bf16 hi/lo split helpers + mma.sync wrapper
// ---------------------------------------------------------------------------
__device__ __forceinline__ void split_pack(float f0, float f1,
                                           unsigned& hi, unsigned& lo)
{
    __nv_bfloat162 h;
    h.x = __float2bfloat16(f0);
    h.y = __float2bfloat16(f1);
    __nv_bfloat162 l;
    l.x = __float2bfloat16(f0 - __bfloat162float(h.x));
    l.y = __float2bfloat16(f1 - __bfloat162float(h.y));
    hi = *reinterpret_cast<unsigned*>(&h);
    lo = *reinterpret_cast<unsigned*>(&l);
}

__device__ __forceinline__ void mma_bf16(float* c, const unsigned* a,
                                         const unsigned* b)
{
    asm volatile(
        "mma.sync.aligned.m16n8k16.row.col.f32.bf16.bf16.f32 "
        "{%0,%1,%2,%3}, {%4,%5,%6,%7}, {%8,%9}, {%0,%1,%2,%3};"
        : "+f"(c[0]), "+f"(c[1]), "+f"(c[2]), "+f"(c[3])
        : "r"(a[0]), "r"(a[1]), "r"(a[2]), "r"(a[3]),
          "r"(b[0]), "r"(b[1]));
}

// ---------------------------------------------------------------------------
// Kernel A: W = SCALE * Q @ K^T   (tensor cores, bf16 3-term split)
// CTA tile 128x128. K(=D)=128 consumed in two 64-wide chunks.
// smem per chunk: Qs[128][68], Ks[128][68] fp32 (both [row][k]).
// 8 warps (2x4), warp tile 64x32.
// ---------------------------------------------------------------------------
#define QK_SMEM ((128 * 68 + 128 * 68) * 4)

__global__ __launch_bounds__(256, 2) void qk_kernel(
    const float* __restrict__ Q, const float* __restrict__ K,
    float* __restrict__ W)
{
    extern __shared__ float sm[];
    float* Qs = sm;                 // [128][68]
    float* Ks = sm + 128 * 68;      // [128][68]

    const int tid  = threadIdx.x;
    const int lane = tid & 31;
    const int warp = tid >> 5;
    const int head = blockIdx.z;
    const int rowBase = blockIdx.y * 128;
    const int colBase = blockIdx.x * 128;

    const float* q = Q + (size_t)head * SS * DD;
    const float* k = K + (size_t)head * SS * DD;
    float*       w = W + (size_t)head * SS * SS;

    const int wr = (warp >> 2) * 64;
    const int wc = (warp & 3) * 32;
    const int g  = lane >> 2;
    const int cq = (lane & 3) * 2;

    float acc[4][4][4];
#pragma unroll
    for (int mi = 0; mi < 4; mi++)
#pragma unroll
        for (int ni = 0; ni < 4; ni++)
#pragma unroll
            for (int t = 0; t < 4; t++) acc[mi][ni][t] = 0.0f;

#pragma unroll
    for (int kk = 0; kk < DD; kk += 64) {
        __syncthreads();
        // Load 128x64 chunks of Q and K (float4 coalesced).
#pragma unroll
        for (int i = 0; i < 8; i++) {
            int pos = tid + i * 256;
            int r   = pos >> 4;          // 0..127
            int c4  = pos & 15;          // 0..15
            *(float4*)&Qs[r * 68 + c4 * 4] =
                *(const float4*)(q + (size_t)(rowBase + r) * DD + kk + c4 * 4);
            *(float4*)&Ks[r * 68 + c4 * 4] =
                *(const float4*)(k + (size_t)(colBase + r) * DD + kk + c4 * 4);
        }
        __syncthreads();

#pragma unroll
        for (int ks = 0; ks < 4; ks++) {
            const int k0 = ks * 16 + cq;

            unsigned bh[4][2], bl[4][2];
#pragma unroll
            for (int ni = 0; ni < 4; ni++) {
                const float* kp = &Ks[(wc + ni * 8 + g) * 68 + k0];
                split_pack(kp[0], kp[1], bh[ni][0], bl[ni][0]);
                split_pack(kp[8], kp[9], bh[ni][1], bl[ni][1]);
            }

#pragma unroll
            for (int mi = 0; mi < 4; mi++) {
                const float* qp = &Qs[(wr + mi * 16 + g) * 68 + k0];
                unsigned ah[4], al[4];
                split_pack(qp[0],           qp[1],           ah[0], al[0]);
                split_pack(qp[8 * 68],      qp[8 * 68 + 1],  ah[1], al[1]);
                split_pack(qp[8],           qp[9],           ah[2], al[2]);
                split_pack(qp[8 * 68 + 8],  qp[8 * 68 + 9],  ah[3], al[3]);
#pragma unroll
                for (int ni = 0; ni < 4; ni++) {
                    mma_bf16(acc[mi][ni], ah, bh[ni]);
                    mma_bf16(acc[mi][ni], ah, bl[ni]);
                    mma_bf16(acc[mi][ni], al, bh[ni]);
                }
            }
        }
    }

    // Epilogue: scale + write.
#pragma unroll
    for (int mi = 0; mi < 4; mi++) {
#pragma unroll
        for (int ni = 0; ni < 4; ni++) {
            int row = rowBase + wr + mi * 16 + g;
            int col = colBase + wc + ni * 8 + cq;
            float2 v0 = { acc[mi][ni][0] * SCALE, acc[mi][ni][1] * SCALE };
            float2 v1 = { acc[mi][ni][2] * SCALE, acc[mi][ni][3] * SCALE };
            *(float2*)(w + (size_t)row * SS + col)       = v0;
            *(float2*)(w + (size_t)(row + 8) * SS + col) = v1;
        }
    }
}

// ---------------------------------------------------------------------------
// Kernel B: in-place row softmax of W. One block per row.
// ---------------------------------------------------------------------------
__global__ __launch_bounds__(256) void softmax_kernel(float* __restrict__ W)
{
    const int tid = threadIdx.x;
    float* w = W + ((size_t)blockIdx.y * SS + blockIdx.x) * SS;

    float v[8];
#pragma unroll
    for (int i = 0; i < 8; i++) v[i] = w[tid + i * 256];

    float m = v[0];
#pragma unroll
    for (int i = 1; i < 8; i++) m = fmaxf(m, v[i]);
#pragma unroll
    for (int o = 16; o > 0; o >>= 1) m = fmaxf(m, __shfl_xor_sync(0xffffffffu, m, o));

    __shared__ float red[8];
    if ((tid & 31) == 0) red[tid >> 5] = m;
    __syncthreads();
    float m2 = red[0];
#pragma unroll
    for (int i = 1; i < 8; i++) m2 = fmaxf(m2, red[i]);
    __syncthreads();

    float s = 0.0f;
#pragma unroll
    for (int i = 0; i < 8; i++) { v[i] = __expf(v[i] - m2); s += v[i]; }
#pragma unroll
    for (int o = 16; o > 0; o >>= 1) s += __shfl_xor_sync(0xffffffffu, s, o);
    if ((tid & 31) == 0) red[tid >> 5] = s;
    __syncthreads();
    float total = 0.0f;
#pragma unroll
    for (int i = 0; i < 8; i++) total += red[i];

    float inv = 1.0f / total;
#pragma unroll
    for (int i = 0; i < 8; i++) w[tid + i * 256] = v[i] * inv;
}

// ---------------------------------------------------------------------------
// Kernel C: O = P @ V  (tensor cores, bf16 3-term split)
// CTA tile 128 rows x 128 cols (N = D = 128). K = 2048 in 64-chunks.
// smem: Ps[128][68] fp32 ([row][k]), Vs[128][65] fp32 ([d][k] transposed).
// ---------------------------------------------------------------------------
#define PV_SMEM ((128 * 68 + 128 * 65) * 4)

__global__ __launch_bounds__(256, 2) void pv_kernel(
    const float* __restrict__ P, const float* __restrict__ V,
    float* __restrict__ O)
{
    extern __shared__ float sm[];
    float* Ps = sm;                 // [128][68]
    float* Vs = sm + 128 * 68;      // [128][65]  (Vs[d][k])

    const int tid  = threadIdx.x;
    const int lane = tid & 31;
    const int warp = tid >> 5;
    const int head = blockIdx.y;
    const int rowBase = blockIdx.x * 128;

    const float* p = P + (size_t)head * SS * SS;
    const float* v = V + (size_t)head * SS * DD;
    float*       o = O + (size_t)head * SS * DD;

    const int wr = (warp >> 2) * 64;
    const int wc = (warp & 3) * 32;
    const int g  = lane >> 2;
    const int cq = (lane & 3) * 2;

    float acc[4][4][4];
#pragma unroll
    for (int mi = 0; mi < 4; mi++)
#pragma unroll
        for (int ni = 0; ni < 4; ni++)
#pragma unroll
            for (int t = 0; t < 4; t++) acc[mi][ni][t] = 0.0f;

    for (int kk = 0; kk < SS; kk += 64) {
        __syncthreads();
        // Load P tile 128x64 (float4 coalesced).
#pragma unroll
        for (int i = 0; i < 8; i++) {
            int pos = tid + i * 256;
            int r   = pos >> 4;
            int c4  = pos & 15;
            *(float4*)&Ps[r * 68 + c4 * 4] =
                *(const float4*)(p + (size_t)(rowBase + r) * SS + kk + c4 * 4);
        }
        // Load V chunk 64x128, transpose into Vs[d][k].
#pragma unroll
        for (int i = 0; i < 32; i++) {
            int pos = tid + i * 256;
            int kl  = pos >> 7;
            int d   = pos & 127;
            Vs[d * 65 + kl] = v[(size_t)(kk + kl) * DD + d];
        }
        __syncthreads();

#pragma unroll
        for (int ks = 0; ks < 4; ks++) {
            const int k0 = ks * 16 + cq;

            unsigned bh[4][2], bl[4][2];
#pragma unroll
            for (int ni = 0; ni < 4; ni++) {
                const float* vp = &Vs[(wc + ni * 8 + g) * 65 + k0];
                split_pack(vp[0], vp[1], bh[ni][0], bl[ni][0]);
                split_pack(vp[8], vp[9], bh[ni][1], bl[ni][1]);
            }

#pragma unroll
            for (int mi = 0; mi < 4; mi++) {
                const float* pp = &Ps[(wr + mi * 16 + g) * 68 + k0];
                unsigned ah[4], al[4];
                split_pack(pp[0],          pp[1],          ah[0], al[0]);
                split_pack(pp[8 * 68],     pp[8 * 68 + 1], ah[1], al[1]);
                split_pack(pp[8],          pp[9],          ah[2], al[2]);
                split_pack(pp[8 * 68 + 8], pp[8 * 68 + 9], ah[3], al[3]);
#pragma unroll
                for (int ni = 0; ni < 4; ni++) {
                    mma_bf16(acc[mi][ni], ah, bh[ni]);
                    mma_bf16(acc[mi][ni], ah, bl[ni]);
                    mma_bf16(acc[mi][ni], al, bh[ni]);
                }
            }
        }
    }

    // Epilogue.
#pragma unroll
    for (int mi = 0; mi < 4; mi++) {
#pragma unroll
        for (int ni = 0; ni < 4; ni++) {
            int row = rowBase + wr + mi * 16 + g;
            int col = wc + ni * 8 + cq;
            float2 v0 = { acc[mi][ni][0], acc[mi][ni][1] };
            float2 v1 = { acc[mi][ni][2], acc[mi][ni][3] };
            *(float2*)(o + (size_t)row * DD + col)       = v0;
            *(float2*)(o + (size_t)(row + 8) * DD + col) = v1;
        }
    }
}

// ---------------------------------------------------------------------------
extern "C" void kernel_launch(void* const* d_in, const int* in_sizes, int n_in,
                              void* d_out, int out_size)
{
    const float* Q = (const float*)d_in[0];
    const float* K = (const float*)d_in[1];
    const float* V = (const float*)d_in[2];

    float* O = (float*)d_out;
    float* W = (float*)d_out + (size_t)NHEAD * SS * DD;

    cudaFuncSetAttribute(qk_kernel, cudaFuncAttributeMaxDynamicSharedMemorySize, QK_SMEM);
    cudaFuncSetAttribute(pv_kernel, cudaFuncAttributeMaxDynamicSharedMemorySize, PV_SMEM);

    qk_kernel<<<dim3(SS / 128, SS / 128, NHEAD), 256, QK_SMEM>>>(Q, K, W);
    softmax_kernel<<<dim3(SS, NHEAD), 256>>>(W);
    pv_kernel<<<dim3(SS / 128, NHEAD), 256, PV_SMEM>>>(W, V, O);
}

// round 4
// speedup vs baseline: 4.7170x; 1.2532x over previous
#include <cuda_runtime.h>
#include <cuda_bf16.h>

#define SS     2048
#define DD     128
#define NHEAD  32
#define SCALE  0.08838834764831845f
#define SA     72      // bf16 row stride in smem planes (144B, conflict-free for ldmatrix)

// ---------------------------------------------------------------------------
// helpers
// ---------------------------------------------------------------------------
__device__ __forceinline__ unsigned smem_u32(const void* p)
{
    return (unsigned)__cvta_generic_to_shared(p);
}

__device__ __forceinline__ void split_pack(float f0, float f1,
                                           unsigned& hi, unsigned& lo)
{
    __nv_bfloat162 h;
    h.x = __float2bfloat16(f0);
    h.y = __float2bfloat16(f1);
    __nv_bfloat162 l;
    l.x = __float2bfloat16(f0 - __bfloat162float(h.x));
    l.y = __float2bfloat16(f1 - __bfloat162float(h.y));
    hi = *reinterpret_cast<unsigned*>(&h);
    lo = *reinterpret_cast<unsigned*>(&l);
}

__device__ __forceinline__ void ldsm_x4(unsigned& r0, unsigned& r1,
                                        unsigned& r2, unsigned& r3,
                                        unsigned addr)
{
    asm volatile("ldmatrix.sync.aligned.m8n8.x4.shared.b16 {%0,%1,%2,%3}, [%4];"
                 : "=r"(r0), "=r"(r1), "=r"(r2), "=r"(r3) : "r"(addr));
}

__device__ __forceinline__ void mma_bf16(float* c, const unsigned* a,
                                         const unsigned* b)
{
    asm volatile(
        "mma.sync.aligned.m16n8k16.row.col.f32.bf16.bf16.f32 "
        "{%0,%1,%2,%3}, {%4,%5,%6,%7}, {%8,%9}, {%0,%1,%2,%3};"
        : "+f"(c[0]), "+f"(c[1]), "+f"(c[2]), "+f"(c[3])
        : "r"(a[0]), "r"(a[1]), "r"(a[2]), "r"(a[3]),
          "r"(b[0]), "r"(b[1]));
}

// Shared compute core: given 4 bf16 smem planes (A hi/lo [128][SA], B hi/lo
// [128][SA], both [row][k], 64-wide k chunk), accumulate the CTA tile.
// 8 warps (2x4): warp tile 64 rows x 32 cols.
struct LaneGeom {
    unsigned aHi[4], aLo[4];   // per mi (A row blocks of 16)
    unsigned bHi[2], bLo[2];   // per ni-pair (B col blocks of 16)
};

__device__ __forceinline__ LaneGeom make_geom(
    const __nv_bfloat16* Ahi, const __nv_bfloat16* Alo,
    const __nv_bfloat16* Bhi, const __nv_bfloat16* Blo,
    int warp, int lane)
{
    const int wr = (warp >> 2) * 64;
    const int wc = (warp & 3) * 32;
    const int rA = (lane & 7) + ((lane >> 3) & 1) * 8;
    const int cA = (lane >> 4) * 8;
    const int rB = (lane & 7) + (lane >> 4) * 8;
    const int cB = ((lane >> 3) & 1) * 8;

    LaneGeom g;
#pragma unroll
    for (int mi = 0; mi < 4; mi++) {
        int row = wr + mi * 16 + rA;
        g.aHi[mi] = smem_u32(&Ahi[row * SA + cA]);
        g.aLo[mi] = smem_u32(&Alo[row * SA + cA]);
    }
#pragma unroll
    for (int np = 0; np < 2; np++) {
        int row = wc + np * 16 + rB;
        g.bHi[np] = smem_u32(&Bhi[row * SA + cB]);
        g.bLo[np] = smem_u32(&Blo[row * SA + cB]);
    }
    return g;
}

__device__ __forceinline__ void chunk_mma(const LaneGeom& g, float acc[4][4][4])
{
#pragma unroll
    for (int ks = 0; ks < 4; ks++) {
        const unsigned off = ks * 32;   // 16 bf16 cols * 2 bytes

        unsigned bh[4][2], bl[4][2];
#pragma unroll
        for (int np = 0; np < 2; np++) {
            ldsm_x4(bh[np*2][0], bh[np*2][1], bh[np*2+1][0], bh[np*2+1][1],
                    g.bHi[np] + off);
            ldsm_x4(bl[np*2][0], bl[np*2][1], bl[np*2+1][0], bl[np*2+1][1],
                    g.bLo[np] + off);
        }

#pragma unroll
        for (int mi = 0; mi < 4; mi++) {
            unsigned ah[4], al[4];
            ldsm_x4(ah[0], ah[1], ah[2], ah[3], g.aHi[mi] + off);
            ldsm_x4(al[0], al[1], al[2], al[3], g.aLo[mi] + off);
#pragma unroll
            for (int ni = 0; ni < 4; ni++) {
                mma_bf16(acc[mi][ni], ah, bh[ni]);
                mma_bf16(acc[mi][ni], ah, bl[ni]);
                mma_bf16(acc[mi][ni], al, bh[ni]);
            }
        }
    }
}

// ---------------------------------------------------------------------------
// Kernel A: W = SCALE * Q @ K^T
// ---------------------------------------------------------------------------
#define PLANES_SMEM (4 * 128 * SA * 2)   // 73728 B

__global__ __launch_bounds__(256, 2) void qk_kernel(
    const float* __restrict__ Q, const float* __restrict__ K,
    float* __restrict__ W)
{
    extern __shared__ __nv_bfloat16 smb[];
    __nv_bfloat16* Qhi = smb;
    __nv_bfloat16* Qlo = Qhi + 128 * SA;
    __nv_bfloat16* Khi = Qlo + 128 * SA;
    __nv_bfloat16* Klo = Khi + 128 * SA;

    const int tid  = threadIdx.x;
    const int lane = tid & 31;
    const int warp = tid >> 5;
    const int head = blockIdx.z;
    const int rowBase = blockIdx.y * 128;
    const int colBase = blockIdx.x * 128;

    const float* q = Q + (size_t)head * SS * DD;
    const float* k = K + (size_t)head * SS * DD;
    float*       w = W + (size_t)head * SS * SS;

    const LaneGeom g = make_geom(Qhi, Qlo, Khi, Klo, warp, lane);

    float acc[4][4][4];
#pragma unroll
    for (int mi = 0; mi < 4; mi++)
#pragma unroll
        for (int ni = 0; ni < 4; ni++)
#pragma unroll
            for (int t = 0; t < 4; t++) acc[mi][ni][t] = 0.0f;

#pragma unroll
    for (int kk = 0; kk < DD; kk += 64) {
        __syncthreads();
        // Load + split 128x64 chunks of Q and K into bf16 planes.
#pragma unroll
        for (int i = 0; i < 8; i++) {
            int pos = tid + i * 256;
            int r   = pos >> 4;          // 0..127
            int c4  = pos & 15;          // 0..15
            float4 qv = *(const float4*)(q + (size_t)(rowBase + r) * DD + kk + c4 * 4);
            unsigned h0, l0, h1, l1;
            split_pack(qv.x, qv.y, h0, l0);
            split_pack(qv.z, qv.w, h1, l1);
            *(uint2*)&Qhi[r * SA + c4 * 4] = make_uint2(h0, h1);
            *(uint2*)&Qlo[r * SA + c4 * 4] = make_uint2(l0, l1);

            float4 kv = *(const float4*)(k + (size_t)(colBase + r) * DD + kk + c4 * 4);
            split_pack(kv.x, kv.y, h0, l0);
            split_pack(kv.z, kv.w, h1, l1);
            *(uint2*)&Khi[r * SA + c4 * 4] = make_uint2(h0, h1);
            *(uint2*)&Klo[r * SA + c4 * 4] = make_uint2(l0, l1);
        }
        __syncthreads();

        chunk_mma(g, acc);
    }

    // Epilogue: scale + write.
    const int wr = (warp >> 2) * 64;
    const int wc = (warp & 3) * 32;
    const int gg = lane >> 2;
    const int cq = (lane & 3) * 2;
#pragma unroll
    for (int mi = 0; mi < 4; mi++) {
#pragma unroll
        for (int ni = 0; ni < 4; ni++) {
            int row = rowBase + wr + mi * 16 + gg;
            int col = colBase + wc + ni * 8 + cq;
            float2 v0 = { acc[mi][ni][0] * SCALE, acc[mi][ni][1] * SCALE };
            float2 v1 = { acc[mi][ni][2] * SCALE, acc[mi][ni][3] * SCALE };
            *(float2*)(w + (size_t)row * SS + col)       = v0;
            *(float2*)(w + (size_t)(row + 8) * SS + col) = v1;
        }
    }
}

// ---------------------------------------------------------------------------
// Kernel B: in-place row softmax of W.
// ---------------------------------------------------------------------------
__global__ __launch_bounds__(256) void softmax_kernel(float* __restrict__ W)
{
    const int tid = threadIdx.x;
    float* w = W + ((size_t)blockIdx.y * SS + blockIdx.x) * SS;

    float v[8];
#pragma unroll
    for (int i = 0; i < 8; i++) v[i] = w[tid + i * 256];

    float m = v[0];
#pragma unroll
    for (int i = 1; i < 8; i++) m = fmaxf(m, v[i]);
#pragma unroll
    for (int o = 16; o > 0; o >>= 1) m = fmaxf(m, __shfl_xor_sync(0xffffffffu, m, o));

    __shared__ float red[8];
    if ((tid & 31) == 0) red[tid >> 5] = m;
    __syncthreads();
    float m2 = red[0];
#pragma unroll
    for (int i = 1; i < 8; i++) m2 = fmaxf(m2, red[i]);
    __syncthreads();

    float s = 0.0f;
#pragma unroll
    for (int i = 0; i < 8; i++) { v[i] = __expf(v[i] - m2); s += v[i]; }
#pragma unroll
    for (int o = 16; o > 0; o >>= 1) s += __shfl_xor_sync(0xffffffffu, s, o);
    if ((tid & 31) == 0) red[tid >> 5] = s;
    __syncthreads();
    float total = 0.0f;
#pragma unroll
    for (int i = 0; i < 8; i++) total += red[i];

    float inv = 1.0f / total;
#pragma unroll
    for (int i = 0; i < 8; i++) w[tid + i * 256] = v[i] * inv;
}

// ---------------------------------------------------------------------------
// Kernel C: O = P @ V
// ---------------------------------------------------------------------------
__global__ __launch_bounds__(256, 2) void pv_kernel(
    const float* __restrict__ P, const float* __restrict__ V,
    float* __restrict__ O)
{
    extern __shared__ __nv_bfloat16 smb[];
    __nv_bfloat16* Phi = smb;
    __nv_bfloat16* Plo = Phi + 128 * SA;
    __nv_bfloat16* Vhi = Plo + 128 * SA;   // [d][k]
    __nv_bfloat16* Vlo = Vhi + 128 * SA;

    const int tid  = threadIdx.x;
    const int lane = tid & 31;
    const int warp = tid >> 5;
    const int head = blockIdx.y;
    const int rowBase = blockIdx.x * 128;

    const float* p = P + (size_t)head * SS * SS;
    const float* v = V + (size_t)head * SS * DD;
    float*       o = O + (size_t)head * SS * DD;

    const LaneGeom g = make_geom(Phi, Plo, Vhi, Vlo, warp, lane);

    float acc[4][4][4];
#pragma unroll
    for (int mi = 0; mi < 4; mi++)
#pragma unroll
        for (int ni = 0; ni < 4; ni++)
#pragma unroll
            for (int t = 0; t < 4; t++) acc[mi][ni][t] = 0.0f;

    for (int kk = 0; kk < SS; kk += 64) {
        __syncthreads();
        // P tile 128x64 (coalesced float4) -> planes.
#pragma unroll
        for (int i = 0; i < 8; i++) {
            int pos = tid + i * 256;
            int r   = pos >> 4;
            int c4  = pos & 15;
            float4 pv4 = *(const float4*)(p + (size_t)(rowBase + r) * SS + kk + c4 * 4);
            unsigned h0, l0, h1, l1;
            split_pack(pv4.x, pv4.y, h0, l0);
            split_pack(pv4.z, pv4.w, h1, l1);
            *(uint2*)&Phi[r * SA + c4 * 4] = make_uint2(h0, h1);
            *(uint2*)&Plo[r * SA + c4 * 4] = make_uint2(l0, l1);
        }
        // V chunk 64x128, transposed into [d][k] planes (k-pairs per thread).
#pragma unroll
        for (int i = 0; i < 16; i++) {
            int pos = tid + i * 256;     // 0..4095
            int kp  = pos >> 7;          // 0..31 (pair of k)
            int d   = pos & 127;
            float a = v[(size_t)(kk + 2 * kp)     * DD + d];
            float b = v[(size_t)(kk + 2 * kp + 1) * DD + d];
            unsigned h, l;
            split_pack(a, b, h, l);
            *(unsigned*)&Vhi[d * SA + 2 * kp] = h;
            *(unsigned*)&Vlo[d * SA + 2 * kp] = l;
        }
        __syncthreads();

        chunk_mma(g, acc);
    }

    // Epilogue.
    const int wr = (warp >> 2) * 64;
    const int wc = (warp & 3) * 32;
    const int gg = lane >> 2;
    const int cq = (lane & 3) * 2;
#pragma unroll
    for (int mi = 0; mi < 4; mi++) {
#pragma unroll
        for (int ni = 0; ni < 4; ni++) {
            int row = rowBase + wr + mi * 16 + gg;
            int col = wc + ni * 8 + cq;
            float2 v0 = { acc[mi][ni][0], acc[mi][ni][1] };
            float2 v1 = { acc[mi][ni][2], acc[mi][ni][3] };
            *(float2*)(o + (size_t)row * DD + col)       = v0;
            *(float2*)(o + (size_t)(row + 8) * DD + col) = v1;
        }
    }
}

// ---------------------------------------------------------------------------
extern "C" void kernel_launch(void* const* d_in, const int* in_sizes, int n_in,
                              void* d_out, int out_size)
{
    const float* Q = (const float*)d_in[0];
    const float* K = (const float*)d_in[1];
    const float* V = (const float*)d_in[2];

    float* O = (float*)d_out;
    float* W = (float*)d_out + (size_t)NHEAD * SS * DD;

    cudaFuncSetAttribute(qk_kernel, cudaFuncAttributeMaxDynamicSharedMemorySize, PLANES_SMEM);
    cudaFuncSetAttribute(pv_kernel, cudaFuncAttributeMaxDynamicSharedMemorySize, PLANES_SMEM);

    qk_kernel<<<dim3(SS / 128, SS / 128, NHEAD), 256, PLANES_SMEM>>>(Q, K, W);
    softmax_kernel<<<dim3(SS, NHEAD), 256>>>(W);
    pv_kernel<<<dim3(SS / 128, NHEAD), 256, PLANES_SMEM>>>(W, V, O);
}

// round 5
// speedup vs baseline: 5.0035x; 1.0607x over previous
#include <cuda_runtime.h>
#include <cuda_bf16.h>

#define SS     2048
#define DD     128
#define NHEAD  32
#define SCALE  0.08838834764831845f
#define CH     32          // k-chunk width
#define SA2    40          // plane row stride (bf16 elems) = 80B, ldmatrix conflict-free
#define PLANE_B (128 * SA2 * 2)          // 10240 B per plane (128 rows)

// pre-split operand planes (hi/lo bf16) in device scratch
__device__ __nv_bfloat16 g_Qhi[(size_t)NHEAD * SS * DD];
__device__ __nv_bfloat16 g_Qlo[(size_t)NHEAD * SS * DD];
__device__ __nv_bfloat16 g_Khi[(size_t)NHEAD * SS * DD];
__device__ __nv_bfloat16 g_Klo[(size_t)NHEAD * SS * DD];
__device__ __nv_bfloat16 g_Vthi[(size_t)NHEAD * DD * SS];   // [head][d][k]
__device__ __nv_bfloat16 g_Vtlo[(size_t)NHEAD * DD * SS];

// ---------------------------------------------------------------------------
// helpers
// ---------------------------------------------------------------------------
__device__ __forceinline__ unsigned smem_u32(const void* p)
{
    return (unsigned)__cvta_generic_to_shared(p);
}

__device__ __forceinline__ void split_pack(float f0, float f1,
                                           unsigned& hi, unsigned& lo)
{
    __nv_bfloat162 h;
    h.x = __float2bfloat16(f0);
    h.y = __float2bfloat16(f1);
    __nv_bfloat162 l;
    l.x = __float2bfloat16(f0 - __bfloat162float(h.x));
    l.y = __float2bfloat16(f1 - __bfloat162float(h.y));
    hi = *reinterpret_cast<unsigned*>(&h);
    lo = *reinterpret_cast<unsigned*>(&l);
}

__device__ __forceinline__ void ldsm_x4(unsigned& r0, unsigned& r1,
                                        unsigned& r2, unsigned& r3,
                                        unsigned addr)
{
    asm volatile("ldmatrix.sync.aligned.m8n8.x4.shared.b16 {%0,%1,%2,%3}, [%4];"
                 : "=r"(r0), "=r"(r1), "=r"(r2), "=r"(r3) : "r"(addr));
}

__device__ __forceinline__ void mma_bf16(float* c, const unsigned* a,
                                         const unsigned* b)
{
    asm volatile(
        "mma.sync.aligned.m16n8k16.row.col.f32.bf16.bf16.f32 "
        "{%0,%1,%2,%3}, {%4,%5,%6,%7}, {%8,%9}, {%0,%1,%2,%3};"
        : "+f"(c[0]), "+f"(c[1]), "+f"(c[2]), "+f"(c[3])
        : "r"(a[0]), "r"(a[1]), "r"(a[2]), "r"(a[3]),
          "r"(b[0]), "r"(b[1]));
}

#define CP16(dst, src) \
    asm volatile("cp.async.cg.shared.global [%0], [%1], 16;" :: "r"(dst), "l"(src))
#define CP_COMMIT  asm volatile("cp.async.commit_group;")
#define CP_WAIT1   asm volatile("cp.async.wait_group 1;")
#define CP_WAIT0   asm volatile("cp.async.wait_group 0;")

// lane offsets (bytes) for ldmatrix fragments inside a [128][SA2] plane
struct LaneOff { int a[4]; int b[2]; };

__device__ __forceinline__ LaneOff make_off(int warp, int lane)
{
    const int wr = (warp >> 2) * 64;
    const int wc = (warp & 3) * 32;
    const int rA = (lane & 7) + ((lane >> 3) & 1) * 8;
    const int cA = (lane >> 4) * 8;
    const int rB = (lane & 7) + (lane >> 4) * 8;
    const int cB = ((lane >> 3) & 1) * 8;
    LaneOff o;
#pragma unroll
    for (int mi = 0; mi < 4; mi++) o.a[mi] = ((wr + mi * 16 + rA) * SA2 + cA) * 2;
#pragma unroll
    for (int np = 0; np < 2; np++) o.b[np] = ((wc + np * 16 + rB) * SA2 + cB) * 2;
    return o;
}

// one 32-wide k-chunk of MMAs (2 k16-steps), 3-term split
__device__ __forceinline__ void mma_chunk(
    unsigned aHiB, unsigned aLoB, unsigned bHiB, unsigned bLoB,
    const LaneOff& o, float acc[4][4][4])
{
#pragma unroll
    for (int ks = 0; ks < 2; ks++) {
        const unsigned off = ks * 32;
        unsigned bh[4][2], bl[4][2];
        ldsm_x4(bh[0][0], bh[0][1], bh[1][0], bh[1][1], bHiB + o.b[0] + off);
        ldsm_x4(bh[2][0], bh[2][1], bh[3][0], bh[3][1], bHiB + o.b[1] + off);
        ldsm_x4(bl[0][0], bl[0][1], bl[1][0], bl[1][1], bLoB + o.b[0] + off);
        ldsm_x4(bl[2][0], bl[2][1], bl[3][0], bl[3][1], bLoB + o.b[1] + off);
#pragma unroll
        for (int mi = 0; mi < 4; mi++) {
            unsigned ah[4], al[4];
            ldsm_x4(ah[0], ah[1], ah[2], ah[3], aHiB + o.a[mi] + off);
            ldsm_x4(al[0], al[1], al[2], al[3], aLoB + o.a[mi] + off);
#pragma unroll
            for (int ni = 0; ni < 4; ni++) {
                mma_bf16(acc[mi][ni], ah, bh[ni]);
                mma_bf16(acc[mi][ni], ah, bl[ni]);
                mma_bf16(acc[mi][ni], al, bh[ni]);
            }
        }
    }
}

// ---------------------------------------------------------------------------
// prep kernels: split Q,K into planes; split+transpose V into [d][k] planes
// ---------------------------------------------------------------------------
__global__ __launch_bounds__(256) void prep_qk(
    const float* __restrict__ Q, const float* __restrict__ K)
{
    size_t idx = (size_t)blockIdx.x * 256 + threadIdx.x;   // float4 index
    float4 qv = ((const float4*)Q)[idx];
    unsigned h0, l0, h1, l1;
    split_pack(qv.x, qv.y, h0, l0);
    split_pack(qv.z, qv.w, h1, l1);
    ((uint2*)g_Qhi)[idx] = make_uint2(h0, h1);
    ((uint2*)g_Qlo)[idx] = make_uint2(l0, l1);
    float4 kv = ((const float4*)K)[idx];
    split_pack(kv.x, kv.y, h0, l0);
    split_pack(kv.z, kv.w, h1, l1);
    ((uint2*)g_Khi)[idx] = make_uint2(h0, h1);
    ((uint2*)g_Klo)[idx] = make_uint2(l0, l1);
}

__global__ __launch_bounds__(256) void prep_v(const float* __restrict__ V)
{
    __shared__ float T[32][33];
    const int tid  = threadIdx.x;
    const int head = blockIdx.z;
    const int k0   = blockIdx.x * 32;
    const int d0   = blockIdx.y * 32;
    const float* v = V + (size_t)head * SS * DD;

#pragma unroll
    for (int p = 0; p < 4; p++) {
        int kl = (tid >> 5) + p * 8;
        int dl = tid & 31;
        T[dl][kl] = v[(size_t)(k0 + kl) * DD + d0 + dl];
    }
    __syncthreads();
#pragma unroll
    for (int p = 0; p < 4; p++) {
        int dl = (tid >> 5) + p * 8;
        int kl = tid & 31;
        float f = T[dl][kl];
        __nv_bfloat16 h = __float2bfloat16(f);
        __nv_bfloat16 l = __float2bfloat16(f - __bfloat162float(h));
        size_t out = ((size_t)head * DD + d0 + dl) * SS + k0 + kl;
        g_Vthi[out] = h;
        g_Vtlo[out] = l;
    }
}

// ---------------------------------------------------------------------------
// Kernel A: W = SCALE * Q @ K^T   (pure bf16, cp.async 2-stage pipeline)
// smem: 2 stages x 4 planes (Qhi,Qlo,Khi,Klo) of [128][SA2] bf16 = 81920 B
// ---------------------------------------------------------------------------
#define QK_STAGE_B (4 * PLANE_B)            // 40960
#define QK_SMEM    (2 * QK_STAGE_B)         // 81920

__global__ __launch_bounds__(256, 2) void qk_kernel(float* __restrict__ W)
{
    extern __shared__ __nv_bfloat16 smb[];
    const unsigned base = smem_u32(smb);

    const int tid  = threadIdx.x;
    const int lane = tid & 31;
    const int warp = tid >> 5;
    const int head = blockIdx.z;
    const int rowBase = blockIdx.y * 128;
    const int colBase = blockIdx.x * 128;

    float* w = W + (size_t)head * SS * SS;

    // per-thread cp.async mapping: 8 x 16B ops per chunk
    const size_t qoff = ((size_t)head * SS + rowBase) * DD;
    const size_t koff = ((size_t)head * SS + colBase) * DD;
    const __nv_bfloat16* srcP[8];
    unsigned dstOff[8];
#pragma unroll
    for (int i = 0; i < 8; i++) {
        int idx = tid + i * 256;
        int seg = idx & 3;
        int r   = (idx >> 2) & 127;
        int pl  = idx >> 9;
        const __nv_bfloat16* bp =
            pl == 0 ? g_Qhi + qoff : pl == 1 ? g_Qlo + qoff :
            pl == 2 ? g_Khi + koff : g_Klo + koff;
        srcP[i]   = bp + (size_t)r * DD + seg * 8;
        dstOff[i] = pl * PLANE_B + r * (SA2 * 2) + seg * 16;
    }

    const LaneOff lo = make_off(warp, lane);

    float acc[4][4][4];
#pragma unroll
    for (int mi = 0; mi < 4; mi++)
#pragma unroll
        for (int ni = 0; ni < 4; ni++)
#pragma unroll
            for (int t = 0; t < 4; t++) acc[mi][ni][t] = 0.0f;

    // prologue: chunk 0 -> stage 0
#pragma unroll
    for (int i = 0; i < 8; i++)
        CP16(base + dstOff[i], srcP[i]);
    CP_COMMIT;

    const int NCH = DD / CH;   // 4
#pragma unroll
    for (int c = 0; c < NCH; c++) {
        __syncthreads();                        // stage (c+1)&1 free (reads done)
        if (c + 1 < NCH) {
            const unsigned sb = base + ((c + 1) & 1) * QK_STAGE_B;
#pragma unroll
            for (int i = 0; i < 8; i++)
                CP16(sb + dstOff[i], srcP[i] + (c + 1) * CH);
            CP_COMMIT;
            CP_WAIT1;                           // chunk c arrived
        } else {
            CP_WAIT0;
        }
        __syncthreads();

        const unsigned st = base + (c & 1) * QK_STAGE_B;
        mma_chunk(st, st + PLANE_B, st + 2 * PLANE_B, st + 3 * PLANE_B, lo, acc);
    }

    // epilogue: scale + write
    const int wr = (warp >> 2) * 64;
    const int wc = (warp & 3) * 32;
    const int gg = lane >> 2;
    const int cq = (lane & 3) * 2;
#pragma unroll
    for (int mi = 0; mi < 4; mi++) {
#pragma unroll
        for (int ni = 0; ni < 4; ni++) {
            int row = rowBase + wr + mi * 16 + gg;
            int col = colBase + wc + ni * 8 + cq;
            float2 v0 = { acc[mi][ni][0] * SCALE, acc[mi][ni][1] * SCALE };
            float2 v1 = { acc[mi][ni][2] * SCALE, acc[mi][ni][3] * SCALE };
            *(float2*)(w + (size_t)row * SS + col)       = v0;
            *(float2*)(w + (size_t)(row + 8) * SS + col) = v1;
        }
    }
}

// ---------------------------------------------------------------------------
// Kernel B: in-place row softmax of W
// ---------------------------------------------------------------------------
__global__ __launch_bounds__(256) void softmax_kernel(float* __restrict__ W)
{
    const int tid = threadIdx.x;
    float* w = W + ((size_t)blockIdx.y * SS + blockIdx.x) * SS;

    float v[8];
#pragma unroll
    for (int i = 0; i < 8; i++) v[i] = w[tid + i * 256];

    float m = v[0];
#pragma unroll
    for (int i = 1; i < 8; i++) m = fmaxf(m, v[i]);
#pragma unroll
    for (int o = 16; o > 0; o >>= 1) m = fmaxf(m, __shfl_xor_sync(0xffffffffu, m, o));

    __shared__ float red[8];
    if ((tid & 31) == 0) red[tid >> 5] = m;
    __syncthreads();
    float m2 = red[0];
#pragma unroll
    for (int i = 1; i < 8; i++) m2 = fmaxf(m2, red[i]);
    __syncthreads();

    float s = 0.0f;
#pragma unroll
    for (int i = 0; i < 8; i++) { v[i] = __expf(v[i] - m2); s += v[i]; }
#pragma unroll
    for (int o = 16; o > 0; o >>= 1) s += __shfl_xor_sync(0xffffffffu, s, o);
    if ((tid & 31) == 0) red[tid >> 5] = s;
    __syncthreads();
    float total = 0.0f;
#pragma unroll
    for (int i = 0; i < 8; i++) total += red[i];

    float inv = 1.0f / total;
#pragma unroll
    for (int i = 0; i < 8; i++) w[tid + i * 256] = v[i] * inv;
}

// ---------------------------------------------------------------------------
// Kernel C: O = P @ V  (cp.async fp32 P staging + in-smem split, V pre-split)
// smem: Pf32 2x18432 | Pplanes hi/lo 2x10240 | Vplanes 2 stages x 2 x 10240
// ---------------------------------------------------------------------------
#define PF32_ST_B  (128 * 36 * 4)                   // 18432
#define PV_PF0     0
#define PV_PPHI    (2 * PF32_ST_B)                  // 36864
#define PV_PPLO    (PV_PPHI + PLANE_B)              // 47104
#define PV_VST     (PV_PPLO + PLANE_B)              // 57344
#define PV_VSTAGE  (2 * PLANE_B)                    // 20480
#define PV_SMEM    (PV_VST + 2 * PV_VSTAGE)         // 98304

__global__ __launch_bounds__(256, 2) void pv_kernel(
    const float* __restrict__ P, float* __restrict__ O)
{
    extern __shared__ __nv_bfloat16 smb[];
    float* smf = (float*)smb;
    const unsigned base = smem_u32(smb);

    const int tid  = threadIdx.x;
    const int lane = tid & 31;
    const int warp = tid >> 5;
    const int head = blockIdx.y;
    const int rowBase = blockIdx.x * 128;

    const float* p = P + (size_t)head * SS * SS;
    float*       o = O + (size_t)head * SS * DD;

    // cp.async mapping: 4 P-fp32 ops + 4 V-plane ops per thread per chunk
    const float* psrc[4];
    unsigned pdst[4];
#pragma unroll
    for (int i = 0; i < 4; i++) {
        int idx = tid + i * 256;          // 0..1023
        int seg = idx & 7;
        int r   = idx >> 3;
        psrc[i] = p + (size_t)(rowBase + r) * SS + seg * 4;
        pdst[i] = r * 144 + seg * 16;
    }
    const __nv_bfloat16* vsrc[4];
    unsigned vdst[4];
#pragma unroll
    for (int i = 0; i < 4; i++) {
        int idx = tid + i * 256;
        int seg = idx & 3;
        int d   = (idx >> 2) & 127;
        int pl  = idx >> 9;
        const __nv_bfloat16* bp = pl ? g_Vtlo : g_Vthi;
        vsrc[i] = bp + ((size_t)head * DD + d) * SS + seg * 8;
        vdst[i] = pl * PLANE_B + d * (SA2 * 2) + seg * 16;
    }

    const LaneOff lof = make_off(warp, lane);

    float acc[4][4][4];
#pragma unroll
    for (int mi = 0; mi < 4; mi++)
#pragma unroll
        for (int ni = 0; ni < 4; ni++)
#pragma unroll
            for (int t = 0; t < 4; t++) acc[mi][ni][t] = 0.0f;

    // prologue: chunk 0 -> stage 0
#pragma unroll
    for (int i = 0; i < 4; i++) CP16(base + PV_PF0 + pdst[i], psrc[i]);
#pragma unroll
    for (int i = 0; i < 4; i++) CP16(base + PV_VST + vdst[i], vsrc[i]);
    CP_COMMIT;

    const int NCH = SS / CH;   // 64
    for (int c = 0; c < NCH; c++) {
        __syncthreads();
        if (c + 1 < NCH) {
            int st1 = (c + 1) & 1;
#pragma unroll
            for (int i = 0; i < 4; i++)
                CP16(base + PV_PF0 + st1 * PF32_ST_B + pdst[i],
                     psrc[i] + (c + 1) * CH);
#pragma unroll
            for (int i = 0; i < 4; i++)
                CP16(base + PV_VST + st1 * PV_VSTAGE + vdst[i],
                     vsrc[i] + (c + 1) * CH);
            CP_COMMIT;
            CP_WAIT1;
        } else {
            CP_WAIT0;
        }
        __syncthreads();

        // split P fp32 stage -> Pplanes (bf16 hi/lo)
        const int st = c & 1;
        float* pf = smf + st * (PF32_ST_B / 4);
        __nv_bfloat16* phi = smb + PV_PPHI / 2;
        __nv_bfloat16* plo = smb + PV_PPLO / 2;
#pragma unroll
        for (int i = 0; i < 4; i++) {
            int pos = tid + i * 256;
            int r   = pos >> 3;
            int c4  = pos & 7;
            float4 f = *(float4*)(pf + r * 36 + c4 * 4);
            unsigned h0, l0, h1, l1;
            split_pack(f.x, f.y, h0, l0);
            split_pack(f.z, f.w, h1, l1);
            *(uint2*)(phi + r * SA2 + c4 * 4) = make_uint2(h0, h1);
            *(uint2*)(plo + r * SA2 + c4 * 4) = make_uint2(l0, l1);
        }
        __syncthreads();

        const unsigned vb = base + PV_VST + st * PV_VSTAGE;
        mma_chunk(base + PV_PPHI, base + PV_PPLO, vb, vb + PLANE_B, lof, acc);
    }

    // epilogue
    const int wr = (warp >> 2) * 64;
    const int wc = (warp & 3) * 32;
    const int gg = lane >> 2;
    const int cq = (lane & 3) * 2;
#pragma unroll
    for (int mi = 0; mi < 4; mi++) {
#pragma unroll
        for (int ni = 0; ni < 4; ni++) {
            int row = rowBase + wr + mi * 16 + gg;
            int col = wc + ni * 8 + cq;
            float2 v0 = { acc[mi][ni][0], acc[mi][ni][1] };
            float2 v1 = { acc[mi][ni][2], acc[mi][ni][3] };
            *(float2*)(o + (size_t)row * DD + col)       = v0;
            *(float2*)(o + (size_t)(row + 8) * DD + col) = v1;
        }
    }
}

// ---------------------------------------------------------------------------
extern "C" void kernel_launch(void* const* d_in, const int* in_sizes, int n_in,
                              void* d_out, int out_size)
{
    const float* Q = (const float*)d_in[0];
    const float* K = (const float*)d_in[1];
    const float* V = (const float*)d_in[2];

    float* O = (float*)d_out;
    float* W = (float*)d_out + (size_t)NHEAD * SS * DD;

    cudaFuncSetAttribute(qk_kernel, cudaFuncAttributeMaxDynamicSharedMemorySize, QK_SMEM);
    cudaFuncSetAttribute(pv_kernel, cudaFuncAttributeMaxDynamicSharedMemorySize, PV_SMEM);

    prep_qk<<<(NHEAD * SS * DD / 4) / 256, 256>>>(Q, K);
    prep_v<<<dim3(SS / 32, DD / 32, NHEAD), 256>>>(V);
    qk_kernel<<<dim3(SS / 128, SS / 128, NHEAD), 256, QK_SMEM>>>(W);
    softmax_kernel<<<dim3(SS, NHEAD), 256>>>(W);
    pv_kernel<<<dim3(SS / 128, NHEAD), 256, PV_SMEM>>>(W, O);
}

// round 7
// speedup vs baseline: 5.2449x; 1.0483x over previous
#include <cuda_runtime.h>
#include <cuda_bf16.h>
#include <cstdint>

#define SS     2048
#define DD     128
#define NHEAD  32
#define SCALE  0.08838834764831845f
#define CH     32          // k-chunk width
#define SA2    40          // plane row stride (bf16 elems) = 80B, ldmatrix conflict-free
#define PLANE_B (128 * SA2 * 2)          // 10240 B per plane

// pre-split operand planes (hi/lo bf16) in device scratch
__device__ __nv_bfloat16 g_Qhi[(size_t)NHEAD * SS * DD];
__device__ __nv_bfloat16 g_Qlo[(size_t)NHEAD * SS * DD];
__device__ __nv_bfloat16 g_Khi[(size_t)NHEAD * SS * DD];
__device__ __nv_bfloat16 g_Klo[(size_t)NHEAD * SS * DD];
__device__ __nv_bfloat16 g_Vthi[(size_t)NHEAD * DD * SS];   // [head][d][k]
__device__ __nv_bfloat16 g_Vtlo[(size_t)NHEAD * DD * SS];

// ---------------------------------------------------------------------------
// helpers
// ---------------------------------------------------------------------------
__device__ __forceinline__ unsigned smem_u32(const void* p)
{
    return (unsigned)__cvta_generic_to_shared(p);
}

__device__ __forceinline__ void split_pack(float f0, float f1,
                                           unsigned& hi, unsigned& lo)
{
    __nv_bfloat162 h;
    h.x = __float2bfloat16(f0);
    h.y = __float2bfloat16(f1);
    __nv_bfloat162 l;
    l.x = __float2bfloat16(f0 - __bfloat162float(h.x));
    l.y = __float2bfloat16(f1 - __bfloat162float(h.y));
    hi = *reinterpret_cast<unsigned*>(&h);
    lo = *reinterpret_cast<unsigned*>(&l);
}

__device__ __forceinline__ void ldsm_x4(unsigned& r0, unsigned& r1,
                                        unsigned& r2, unsigned& r3,
                                        unsigned addr)
{
    asm volatile("ldmatrix.sync.aligned.m8n8.x4.shared.b16 {%0,%1,%2,%3}, [%4];"
                 : "=r"(r0), "=r"(r1), "=r"(r2), "=r"(r3) : "r"(addr));
}

__device__ __forceinline__ void mma_bf16(float* c, const unsigned* a,
                                         const unsigned* b)
{
    asm volatile(
        "mma.sync.aligned.m16n8k16.row.col.f32.bf16.bf16.f32 "
        "{%0,%1,%2,%3}, {%4,%5,%6,%7}, {%8,%9}, {%0,%1,%2,%3};"
        : "+f"(c[0]), "+f"(c[1]), "+f"(c[2]), "+f"(c[3])
        : "r"(a[0]), "r"(a[1]), "r"(a[2]), "r"(a[3]),
          "r"(b[0]), "r"(b[1]));
}

#define CP16(dst, src) \
    asm volatile("cp.async.cg.shared.global [%0], [%1], 16;" :: "r"(dst), "l"(src))
#define CP_COMMIT  asm volatile("cp.async.commit_group;")
#define CP_WAIT1   asm volatile("cp.async.wait_group 1;")
#define CP_WAIT0   asm volatile("cp.async.wait_group 0;")

// lane offsets (bytes) for ldmatrix fragments inside a [128][SA2] plane
struct LaneOff { int a[4]; int b[2]; };

__device__ __forceinline__ LaneOff make_off(int warp, int lane)
{
    const int wr = (warp >> 2) * 64;
    const int wc = (warp & 3) * 32;
    const int rA = (lane & 7) + ((lane >> 3) & 1) * 8;
    const int cA = (lane >> 4) * 8;
    const int rB = (lane & 7) + (lane >> 4) * 8;
    const int cB = ((lane >> 3) & 1) * 8;
    LaneOff o;
#pragma unroll
    for (int mi = 0; mi < 4; mi++) o.a[mi] = ((wr + mi * 16 + rA) * SA2 + cA) * 2;
#pragma unroll
    for (int np = 0; np < 2; np++) o.b[np] = ((wc + np * 16 + rB) * SA2 + cB) * 2;
    return o;
}

// one 32-wide k-chunk of MMAs (2 k16-steps), 3-term split
__device__ __forceinline__ void mma_chunk(
    unsigned aHiB, unsigned aLoB, unsigned bHiB, unsigned bLoB,
    const LaneOff& o, float acc[4][4][4])
{
#pragma unroll
    for (int ks = 0; ks < 2; ks++) {
        const unsigned off = ks * 32;
        unsigned bh[4][2], bl[4][2];
        ldsm_x4(bh[0][0], bh[0][1], bh[1][0], bh[1][1], bHiB + o.b[0] + off);
        ldsm_x4(bh[2][0], bh[2][1], bh[3][0], bh[3][1], bHiB + o.b[1] + off);
        ldsm_x4(bl[0][0], bl[0][1], bl[1][0], bl[1][1], bLoB + o.b[0] + off);
        ldsm_x4(bl[2][0], bl[2][1], bl[3][0], bl[3][1], bLoB + o.b[1] + off);
#pragma unroll
        for (int mi = 0; mi < 4; mi++) {
            unsigned ah[4], al[4];
            ldsm_x4(ah[0], ah[1], ah[2], ah[3], aHiB + o.a[mi] + off);
            ldsm_x4(al[0], al[1], al[2], al[3], aLoB + o.a[mi] + off);
#pragma unroll
            for (int ni = 0; ni < 4; ni++) {
                mma_bf16(acc[mi][ni], ah, bh[ni]);
                mma_bf16(acc[mi][ni], ah, bl[ni]);
                mma_bf16(acc[mi][ni], al, bh[ni]);
            }
        }
    }
}

// ---------------------------------------------------------------------------
// prep kernels (SCALE folded into Q planes)
// ---------------------------------------------------------------------------
__global__ __launch_bounds__(256) void prep_qk(
    const float* __restrict__ Q, const float* __restrict__ K)
{
    size_t idx = (size_t)blockIdx.x * 256 + threadIdx.x;
    float4 qv = ((const float4*)Q)[idx];
    unsigned h0, l0, h1, l1;
    split_pack(qv.x * SCALE, qv.y * SCALE, h0, l0);
    split_pack(qv.z * SCALE, qv.w * SCALE, h1, l1);
    ((uint2*)g_Qhi)[idx] = make_uint2(h0, h1);
    ((uint2*)g_Qlo)[idx] = make_uint2(l0, l1);
    float4 kv = ((const float4*)K)[idx];
    split_pack(kv.x, kv.y, h0, l0);
    split_pack(kv.z, kv.w, h1, l1);
    ((uint2*)g_Khi)[idx] = make_uint2(h0, h1);
    ((uint2*)g_Klo)[idx] = make_uint2(l0, l1);
}

__global__ __launch_bounds__(256) void prep_v(const float* __restrict__ V)
{
    __shared__ float T[32][33];
    const int tid  = threadIdx.x;
    const int head = blockIdx.z;
    const int k0   = blockIdx.x * 32;
    const int d0   = blockIdx.y * 32;
    const float* v = V + (size_t)head * SS * DD;

#pragma unroll
    for (int p = 0; p < 4; p++) {
        int kl = (tid >> 5) + p * 8;
        int dl = tid & 31;
        T[dl][kl] = v[(size_t)(k0 + kl) * DD + d0 + dl];
    }
    __syncthreads();
#pragma unroll
    for (int p = 0; p < 4; p++) {
        int dl = (tid >> 5) + p * 8;
        int kl = tid & 31;
        float f = T[dl][kl];
        __nv_bfloat16 h = __float2bfloat16(f);
        __nv_bfloat16 l = __float2bfloat16(f - __bfloat162float(h));
        size_t out = ((size_t)head * DD + d0 + dl) * SS + k0 + kl;
        g_Vthi[out] = h;
        g_Vtlo[out] = l;
    }
}

// ---------------------------------------------------------------------------
// Kernel A: W = Q' @ K^T  (pure bf16 planes, cp.async 2-stage pipeline)
// ---------------------------------------------------------------------------
#define QK_STAGE_B (4 * PLANE_B)
#define QK_SMEM    (2 * QK_STAGE_B)

__global__ __launch_bounds__(256, 2) void qk_kernel(float* __restrict__ W)
{
    extern __shared__ __nv_bfloat16 smb[];
    const unsigned base = smem_u32(smb);

    const int tid  = threadIdx.x;
    const int lane = tid & 31;
    const int warp = tid >> 5;
    const int head = blockIdx.z;
    const int rowBase = blockIdx.y * 128;
    const int colBase = blockIdx.x * 128;

    float* w = W + (size_t)head * SS * SS;

    const size_t qoff = ((size_t)head * SS + rowBase) * DD;
    const size_t koff = ((size_t)head * SS + colBase) * DD;
    const __nv_bfloat16* srcP[8];
    unsigned dstOff[8];
#pragma unroll
    for (int i = 0; i < 8; i++) {
        int idx = tid + i * 256;
        int seg = idx & 3;
        int r   = (idx >> 2) & 127;
        int pl  = idx >> 9;
        const __nv_bfloat16* bp =
            pl == 0 ? g_Qhi + qoff : pl == 1 ? g_Qlo + qoff :
            pl == 2 ? g_Khi + koff : g_Klo + koff;
        srcP[i]   = bp + (size_t)r * DD + seg * 8;
        dstOff[i] = pl * PLANE_B + r * (SA2 * 2) + seg * 16;
    }

    const LaneOff lo = make_off(warp, lane);

    float acc[4][4][4];
#pragma unroll
    for (int mi = 0; mi < 4; mi++)
#pragma unroll
        for (int ni = 0; ni < 4; ni++)
#pragma unroll
            for (int t = 0; t < 4; t++) acc[mi][ni][t] = 0.0f;

#pragma unroll
    for (int i = 0; i < 8; i++)
        CP16(base + dstOff[i], srcP[i]);
    CP_COMMIT;

    const int NCH = DD / CH;   // 4
#pragma unroll
    for (int c = 0; c < NCH; c++) {
        __syncthreads();
        if (c + 1 < NCH) {
            const unsigned sb = base + ((c + 1) & 1) * QK_STAGE_B;
#pragma unroll
            for (int i = 0; i < 8; i++)
                CP16(sb + dstOff[i], srcP[i] + (c + 1) * CH);
            CP_COMMIT;
            CP_WAIT1;
        } else {
            CP_WAIT0;
        }
        __syncthreads();

        const unsigned st = base + (c & 1) * QK_STAGE_B;
        mma_chunk(st, st + PLANE_B, st + 2 * PLANE_B, st + 3 * PLANE_B, lo, acc);
    }

    const int wr = (warp >> 2) * 64;
    const int wc = (warp & 3) * 32;
    const int gg = lane >> 2;
    const int cq = (lane & 3) * 2;
#pragma unroll
    for (int mi = 0; mi < 4; mi++) {
#pragma unroll
        for (int ni = 0; ni < 4; ni++) {
            int row = rowBase + wr + mi * 16 + gg;
            int col = colBase + wc + ni * 8 + cq;
            float2 v0 = { acc[mi][ni][0], acc[mi][ni][1] };
            float2 v1 = { acc[mi][ni][2], acc[mi][ni][3] };
            *(float2*)(w + (size_t)row * SS + col)       = v0;
            *(float2*)(w + (size_t)(row + 8) * SS + col) = v1;
        }
    }
}

// ---------------------------------------------------------------------------
// Kernel B: in-place row softmax of W
// ---------------------------------------------------------------------------
__global__ __launch_bounds__(256) void softmax_kernel(float* __restrict__ W)
{
    const int tid = threadIdx.x;
    float* w = W + ((size_t)blockIdx.y * SS + blockIdx.x) * SS;

    float v[8];
#pragma unroll
    for (int i = 0; i < 8; i++) v[i] = w[tid + i * 256];

    float m = v[0];
#pragma unroll
    for (int i = 1; i < 8; i++) m = fmaxf(m, v[i]);
#pragma unroll
    for (int o = 16; o > 0; o >>= 1) m = fmaxf(m, __shfl_xor_sync(0xffffffffu, m, o));

    __shared__ float red[8];
    if ((tid & 31) == 0) red[tid >> 5] = m;
    __syncthreads();
    float m2 = red[0];
#pragma unroll
    for (int i = 1; i < 8; i++) m2 = fmaxf(m2, red[i]);
    __syncthreads();

    float s = 0.0f;
#pragma unroll
    for (int i = 0; i < 8; i++) { v[i] = __expf(v[i] - m2); s += v[i]; }
#pragma unroll
    for (int o = 16; o > 0; o >>= 1) s += __shfl_xor_sync(0xffffffffu, s, o);
    if ((tid & 31) == 0) red[tid >> 5] = s;
    __syncthreads();
    float total = 0.0f;
#pragma unroll
    for (int i = 0; i < 8; i++) total += red[i];

    float inv = 1.0f / total;
#pragma unroll
    for (int i = 0; i < 8; i++) w[tid + i * 256] = v[i] * inv;
}

// ---------------------------------------------------------------------------
// Kernel C: O = P @ V
// P: LDG -> registers -> split -> double-buffered bf16 planes (split overlaps
// MMA across warps). V: pre-split planes via cp.async 2-stage ring.
// smem: Ppl[2][2][PLANE_B] (40960) + Vst[2][2][PLANE_B] (40960) = 81920 B
// ---------------------------------------------------------------------------
#define PV_PPL   0
#define PV_PBUF  (2 * PLANE_B)          // one buf = hi+lo
#define PV_VST   (2 * PV_PBUF)          // 40960
#define PV_VSTG  (2 * PLANE_B)
#define PV_SMEM  (PV_VST + 2 * PV_VSTG) // 81920

__global__ __launch_bounds__(256, 2) void pv_kernel(
    const float* __restrict__ P, float* __restrict__ O)
{
    extern __shared__ __nv_bfloat16 smb[];
    const unsigned base = smem_u32(smb);

    const int tid  = threadIdx.x;
    const int lane = tid & 31;
    const int warp = tid >> 5;
    const int head = blockIdx.y;
    const int rowBase = blockIdx.x * 128;

    const float* p = P + (size_t)head * SS * SS;
    float*       o = O + (size_t)head * SS * DD;

    // P LDG mapping: 4 float4 per thread per chunk (128 rows x 32 k)
    const float* psrc[4];
    unsigned pElem[4];   // bf16-element offset in plane: r*SA2 + seg*4
#pragma unroll
    for (int i = 0; i < 4; i++) {
        int idx = tid + i * 256;
        int seg = idx & 7;
        int r   = idx >> 3;
        psrc[i]  = p + (size_t)(rowBase + r) * SS + seg * 4;
        pElem[i] = r * SA2 + seg * 4;
    }
    // V cp.async mapping: 4 x 16B per thread per chunk
    const __nv_bfloat16* vsrc[4];
    unsigned vdst[4];
#pragma unroll
    for (int i = 0; i < 4; i++) {
        int idx = tid + i * 256;
        int seg = idx & 3;
        int d   = (idx >> 2) & 127;
        int pl  = idx >> 9;
        const __nv_bfloat16* bp = pl ? g_Vtlo : g_Vthi;
        vsrc[i] = bp + ((size_t)head * DD + d) * SS + seg * 8;
        vdst[i] = pl * PLANE_B + d * (SA2 * 2) + seg * 16;
    }

    const LaneOff lof = make_off(warp, lane);

    float acc[4][4][4];
#pragma unroll
    for (int mi = 0; mi < 4; mi++)
#pragma unroll
        for (int ni = 0; ni < 4; ni++)
#pragma unroll
            for (int t = 0; t < 4; t++) acc[mi][ni][t] = 0.0f;

    // prologue: V chunk0 cp.async; P chunk0 LDG+split -> pbuf0
#pragma unroll
    for (int i = 0; i < 4; i++) CP16(base + PV_VST + vdst[i], vsrc[i]);
    CP_COMMIT;
    {
        __nv_bfloat16* phi = smb + PV_PPL / 2;
        __nv_bfloat16* plo = phi + PLANE_B / 2;
#pragma unroll
        for (int i = 0; i < 4; i++) {
            float4 f = *(const float4*)psrc[i];
            unsigned h0, l0, h1, l1;
            split_pack(f.x, f.y, h0, l0);
            split_pack(f.z, f.w, h1, l1);
            *(uint2*)(phi + pElem[i]) = make_uint2(h0, h1);
            *(uint2*)(plo + pElem[i]) = make_uint2(l0, l1);
        }
    }

    const int NCH = SS / CH;   // 64
    for (int c = 0; c < NCH; c++) {
        __syncthreads();   // pbuf[c&1] split visible; vst[(c+1)&1] free for reuse
        if (c + 1 < NCH) {
            const unsigned vb1 = base + PV_VST + ((c + 1) & 1) * PV_VSTG;
#pragma unroll
            for (int i = 0; i < 4; i++)
                CP16(vb1 + vdst[i], vsrc[i] + (c + 1) * CH);
            CP_COMMIT;
            CP_WAIT1;      // V chunk c arrived (this thread's ops)
        } else {
            CP_WAIT0;
        }
        __syncthreads();   // V chunk c visible to all threads

        // prefetch P chunk c+1 into registers (hides LDG under MMA)
        float4 n4[4];
        if (c + 1 < NCH) {
#pragma unroll
            for (int i = 0; i < 4; i++)
                n4[i] = *(const float4*)(psrc[i] + (c + 1) * CH);
        }

        const unsigned pb = base + PV_PPL + (c & 1) * PV_PBUF;
        const unsigned vb = base + PV_VST + (c & 1) * PV_VSTG;
        mma_chunk(pb, pb + PLANE_B, vb, vb + PLANE_B, lof, acc);

        if (c + 1 < NCH) {
            __nv_bfloat16* phi = smb + (PV_PPL + ((c + 1) & 1) * PV_PBUF) / 2;
            __nv_bfloat16* plo = phi + PLANE_B / 2;
#pragma unroll
            for (int i = 0; i < 4; i++) {
                unsigned h0, l0, h1, l1;
                split_pack(n4[i].x, n4[i].y, h0, l0);
                split_pack(n4[i].z, n4[i].w, h1, l1);
                *(uint2*)(phi + pElem[i]) = make_uint2(h0, h1);
                *(uint2*)(plo + pElem[i]) = make_uint2(l0, l1);
            }
        }
    }

    // epilogue
    const int wr = (warp >> 2) * 64;
    const int wc = (warp & 3) * 32;
    const int gg = lane >> 2;
    const int cq = (lane & 3) * 2;
#pragma unroll
    for (int mi = 0; mi < 4; mi++) {
#pragma unroll
        for (int ni = 0; ni < 4; ni++) {
            int row = rowBase + wr + mi * 16 + gg;
            int col = wc + ni * 8 + cq;
            float2 v0 = { acc[mi][ni][0], acc[mi][ni][1] };
            float2 v1 = { acc[mi][ni][2], acc[mi][ni][3] };
            *(float2*)(o + (size_t)row * DD + col)       = v0;
            *(float2*)(o + (size_t)(row + 8) * DD + col) = v1;
        }
    }
}

// ---------------------------------------------------------------------------
extern "C" void kernel_launch(void* const* d_in, const int* in_sizes, int n_in,
                              void* d_out, int out_size)
{
    const float* Q = (const float*)d_in[0];
    const float* K = (const float*)d_in[1];
    const float* V = (const float*)d_in[2];

    float* O = (float*)d_out;
    float* W = (float*)d_out + (size_t)NHEAD * SS * DD;

    cudaFuncSetAttribute(qk_kernel, cudaFuncAttributeMaxDynamicSharedMemorySize, QK_SMEM);
    cudaFuncSetAttribute(pv_kernel, cudaFuncAttributeMaxDynamicSharedMemorySize, PV_SMEM);

    prep_qk<<<(NHEAD * SS * DD / 4) / 256, 256>>>(Q, K);
    prep_v<<<dim3(SS / 32, DD / 32, NHEAD), 256>>>(V);
    qk_kernel<<<dim3(SS / 128, SS / 128, NHEAD), 256, QK_SMEM>>>(W);
    softmax_kernel<<<dim3(SS, NHEAD), 256>>>(W);
    pv_kernel<<<dim3(SS / 128, NHEAD), 256, PV_SMEM>>>(W, O);
}